// round 13
// baseline (speedup 1.0000x reference)
#include <cuda_runtime.h>
#include <cstdint>

#define LSEQ 200
#define LP   68

// ---- smem float offsets ----
#define OFF_MS   0              // A tf32 [200][68], later Ms
#define OFF_BF   13600          // B fragments 8*8*66 = 4224 floats (dead after MMA)
#define OFF_WTSI OFF_BF         // [200][4] = 800   (aliases BF in Phase C)
#define OFF_PART (OFF_BF+800)   // [16][3][64] = 3072
#define OFF_CAND (OFF_BF+3872)  // [192]
#define OFF_FAC  (OFF_BF+4064)  // [4]
#define OFF_SMK  (OFF_BF+4068)  // [64]
// allocation covers the LARGEST region above OFF_BF: BF=4224 > pool=4132
#define SMEM_FLOATS (OFF_BF + 4224)   // 17824 floats = 71296 B -> 3 CTAs/SM (213.9KB)

__device__ __forceinline__ uint32_t to_tf32(float x) {
    uint32_t u;
    asm("cvt.rna.tf32.f32 %0, %1;" : "=r"(u) : "f"(x));
    return u;
}

__device__ __forceinline__ void mma_tf32(float& c0, float& c1, float& c2, float& c3,
                                         uint32_t a0, uint32_t a1, uint32_t a2, uint32_t a3,
                                         uint32_t b0, uint32_t b1) {
    asm volatile("mma.sync.aligned.m16n8k8.row.col.f32.tf32.tf32.f32 "
                 "{%0,%1,%2,%3}, {%4,%5,%6,%7}, {%8,%9}, {%0,%1,%2,%3};"
                 : "+f"(c0), "+f"(c1), "+f"(c2), "+f"(c3)
                 : "r"(a0), "r"(a1), "r"(a2), "r"(a3), "r"(b0), "r"(b1));
}

__device__ __forceinline__ float2 ffma2(float2 a, float2 b, float2 c) {
    float2 r;
    asm("fma.rn.f32x2 %0, %1, %2, %3;"
        : "=l"(reinterpret_cast<unsigned long long&>(r))
        : "l"(reinterpret_cast<unsigned long long&>(a)),
          "l"(reinterpret_cast<unsigned long long&>(b)),
          "l"(reinterpret_cast<unsigned long long&>(c)));
    return r;
}

__global__ __launch_bounds__(256, 3)     // <-- the one variable: 3 CTAs/SM (<=85 regs)
void caps_kernel(const float* __restrict__ E,
                 const float* __restrict__ Wg,
                 const float* __restrict__ Lg,
                 const int*   __restrict__ SL,
                 float* __restrict__ out)
{
    extern __shared__ float sm[];
    const int n = blockIdx.x;
    const int t = threadIdx.x;
    const int wid = t >> 5, lane = t & 31;

    // ---- stage B fragments: tile (nb,kb) = 66 floats ----
    {
        const float4* w4 = reinterpret_cast<const float4*>(Wg);
        #pragma unroll 1
        for (int i = 0; i < 4; i++) {
            const int f = t + 256*i;              // f < 1024
            const int d = f >> 4;
            const float4 v = w4[f];
            const float vv[4] = { v.x, v.y, v.z, v.w };
            #pragma unroll
            for (int j = 0; j < 4; j++) {
                const int o = 4*(f & 15) + j;
                const int nb = o >> 3, kb = d >> 3;
                const int ln = ((o & 7) << 2) | (d & 3);
                const int slot = ((d & 7) >> 2);
                sm[OFF_BF + (nb*8 + kb)*66 + ln*2 + slot] =
                    __uint_as_float(to_tf32(vv[j]));
            }
        }
    }

    // ---- stage A row-major [200][68] (tf32), vectorized ----
    {
        const float4* e4 = reinterpret_cast<const float4*>(E + (size_t)n * LSEQ * 64);
        #pragma unroll 1
        for (int i = 0; i < 13; i++) {
            const int f = t + 256*i;              // f < 3200
            if (f < 3200) {
                const int l = f >> 4, q = f & 15;
                const float4 v = e4[f];
                uint4 u;
                u.x = to_tf32(v.x); u.y = to_tf32(v.y);
                u.z = to_tf32(v.z); u.w = to_tf32(v.w);
                *reinterpret_cast<uint4*>(sm + OFF_MS + l*LP + 4*q) = u;
            }
        }
    }

    // logits in registers: thread t owns position l = t (t < 200)
    float lg0 = 0.f, lg1 = 0.f, lg2 = 0.f;
    if (t < LSEQ) {
        const float* lgp = Lg + n*600 + t;
        lg0 = lgp[0]; lg1 = lgp[200]; lg2 = lgp[400];
    }
    const int sl_raw = SL[n];
    const int sl = (sl_raw < 0) ? 0 : ((sl_raw > LSEQ) ? LSEQ : sl_raw);
    __syncthreads();

    // ---- Phase B mma: 8 warps = 4 wm-groups x 2 wn-halves ----
    const int wm = wid >> 1, wn = wid & 1;
    const int mb_base = (wm == 0) ? 0 : (1 + 3*wm);      // 0,4,7,10
    const int mbcnt   = (wm == 0) ? 4 : 3;
    const int r_lo = lane >> 2, c_lo = lane & 3;

    float acc[4][4][4];
    #pragma unroll
    for (int a = 0; a < 4; a++)
        #pragma unroll
        for (int b = 0; b < 4; b++)
            #pragma unroll
            for (int c = 0; c < 4; c++) acc[a][b][c] = 0.f;

    #pragma unroll 1
    for (int kb = 0; kb < 8; kb++) {
        uint32_t bf[4][2];
        #pragma unroll
        for (int nbl = 0; nbl < 4; nbl++) {
            const int nb = wn*4 + nbl;
            const uint2 bv = *reinterpret_cast<const uint2*>(
                sm + OFF_BF + (nb*8 + kb)*66 + lane*2);
            bf[nbl][0] = bv.x; bf[nbl][1] = bv.y;
        }
        #pragma unroll
        for (int mbl = 0; mbl < 4; mbl++) {
            if (mbl < mbcnt) {
                const int mb = mb_base + mbl;
                const float* Ap = sm + OFF_MS + (mb*16 + r_lo)*LP + kb*8 + c_lo;
                const uint32_t a0 = __float_as_uint(Ap[0]);
                const uint32_t a1 = __float_as_uint(Ap[8*LP]);
                const uint32_t a2 = __float_as_uint(Ap[4]);
                const uint32_t a3 = __float_as_uint(Ap[8*LP + 4]);
                #pragma unroll
                for (int nbl = 0; nbl < 4; nbl++)
                    mma_tf32(acc[mbl][nbl][0], acc[mbl][nbl][1],
                             acc[mbl][nbl][2], acc[mbl][nbl][3],
                             a0, a1, a2, a3, bf[nbl][0], bf[nbl][1]);
            }
        }
    }
    __syncthreads();   // MMA reads done; A region becomes Ms, BF becomes Phase-C pool

    // ---- epilogue: accum -> Ms[l][LP] ----
    {
        const int cbase = 2*c_lo;
        #pragma unroll
        for (int mbl = 0; mbl < 4; mbl++) {
            if (mbl < mbcnt) {
                const int mb = mb_base + mbl;
                const int r0 = mb*16 + r_lo, r1 = r0 + 8;
                #pragma unroll
                for (int nbl = 0; nbl < 4; nbl++) {
                    const int nn = (wn*4 + nbl)*8 + cbase;
                    *reinterpret_cast<float2*>(sm + OFF_MS + r0*LP + nn) =
                        make_float2(acc[mbl][nbl][0], acc[mbl][nbl][1]);
                    if (r1 < LSEQ)
                        *reinterpret_cast<float2*>(sm + OFF_MS + r1*LP + nn) =
                            make_float2(acc[mbl][nbl][2], acc[mbl][nbl][3]);
                }
            }
        }
    }
    __syncthreads();

    // ---- masked-tail constant: SMK[o] = (1/3) * sum_{l>=sl} Ms[l][o] ----
    {
        const int o = t & 63, g = t >> 6;         // 4 l-strided groups
        float s = 0.f;
        #pragma unroll 1
        for (int l = g; l < LSEQ; l += 4)
            if (l >= sl) s += sm[OFF_MS + l*LP + o];
        sm[OFF_PART + g*64 + o] = s;
    }
    __syncthreads();
    if (t < 64) {
        sm[OFF_SMK + t] = (sm[OFF_PART + t] + sm[OFF_PART + 64 + t]
                         + sm[OFF_PART + 128 + t] + sm[OFF_PART + 192 + t]) * (1.f/3.f);
    }
    __syncthreads();

    // ---- Phase C: 3 routing iterations, active positions (l < sl) only ----
    const bool valid = (t < sl);

    #pragma unroll 1
    for (int iter = 0; iter < 3; iter++) {
        if (valid) {
            const float m  = fmaxf(lg0, fmaxf(lg1, lg2));
            const float e0 = __expf(lg0 - m), e1 = __expf(lg1 - m), e2 = __expf(lg2 - m);
            const float inv = __frcp_rn(e0 + e1 + e2);
            *reinterpret_cast<float4*>(sm + OFF_WTSI + 4*t) =
                make_float4(e0*inv, e1*inv, e2*inv, 0.f);
        }
        __syncthreads();

        // candidate partials, load-balanced: thread (o4, lq) covers l = lq + 16j
        {
            const int o4 = t & 15, lq = t >> 4;
            float2 c[3][2];
            #pragma unroll
            for (int k = 0; k < 3; k++) { c[k][0] = make_float2(0.f,0.f); c[k][1] = make_float2(0.f,0.f); }
            #pragma unroll 1
            for (int l = lq; l < sl; l += 16) {
                const float4 m4 = *reinterpret_cast<const float4*>(sm + OFF_MS + l*LP + 4*o4);
                const float4 wv = *reinterpret_cast<const float4*>(sm + OFF_WTSI + 4*l);
                const float2 mlo = make_float2(m4.x, m4.y), mhi = make_float2(m4.z, m4.w);
                c[0][0] = ffma2(make_float2(wv.x, wv.x), mlo, c[0][0]);
                c[0][1] = ffma2(make_float2(wv.x, wv.x), mhi, c[0][1]);
                c[1][0] = ffma2(make_float2(wv.y, wv.y), mlo, c[1][0]);
                c[1][1] = ffma2(make_float2(wv.y, wv.y), mhi, c[1][1]);
                c[2][0] = ffma2(make_float2(wv.z, wv.z), mlo, c[2][0]);
                c[2][1] = ffma2(make_float2(wv.z, wv.z), mhi, c[2][1]);
            }
            #pragma unroll
            for (int k = 0; k < 3; k++)
                *reinterpret_cast<float4*>(sm + OFF_PART + (lq*3 + k)*64 + 4*o4) =
                    make_float4(c[k][0].x, c[k][0].y, c[k][1].x, c[k][1].y);
        }
        __syncthreads();

        if (t < 192) {
            const int k = t >> 6, o = t & 63;
            float s = sm[OFF_SMK + o];            // masked-tail constant
            #pragma unroll
            for (int lq = 0; lq < 16; lq++) s += sm[OFF_PART + (lq*3 + k)*64 + o];
            sm[OFF_CAND + t] = s;
        }
        __syncthreads();

        if (t < 96) {
            const int k = t >> 5, ln = t & 31;
            const float v1 = sm[OFF_CAND + k*64 + ln];
            const float v2 = sm[OFF_CAND + k*64 + 32 + ln];
            float s = v1*v1 + v2*v2;
            #pragma unroll
            for (int off = 16; off; off >>= 1) s += __shfl_xor_sync(0xffffffffu, s, off);
            if (ln == 0) sm[OFF_FAC + k] = s / ((1.f + s) * sqrtf(s + 1e-8f));
        }
        __syncthreads();

        if (iter < 2) {
            if (valid) {                           // masked logits never used again
                const float4* ml = reinterpret_cast<const float4*>(sm + OFF_MS + t*LP);
                const float4* c0 = reinterpret_cast<const float4*>(sm + OFF_CAND);
                const float4* c1 = reinterpret_cast<const float4*>(sm + OFF_CAND + 64);
                const float4* c2 = reinterpret_cast<const float4*>(sm + OFF_CAND + 128);
                float2 a0 = make_float2(0.f,0.f), a1 = make_float2(0.f,0.f), a2 = make_float2(0.f,0.f);
                #pragma unroll 4
                for (int q = 0; q < 16; q++) {
                    const float4 m = ml[q];
                    const float2 mlo = make_float2(m.x, m.y), mhi = make_float2(m.z, m.w);
                    const float4 x0 = c0[q], x1 = c1[q], x2 = c2[q];
                    a0 = ffma2(mlo, make_float2(x0.x, x0.y), a0);
                    a0 = ffma2(mhi, make_float2(x0.z, x0.w), a0);
                    a1 = ffma2(mlo, make_float2(x1.x, x1.y), a1);
                    a1 = ffma2(mhi, make_float2(x1.z, x1.w), a1);
                    a2 = ffma2(mlo, make_float2(x2.x, x2.y), a2);
                    a2 = ffma2(mhi, make_float2(x2.z, x2.w), a2);
                }
                const float f0 = sm[OFF_FAC], f1 = sm[OFF_FAC + 1], f2 = sm[OFF_FAC + 2];
                lg0 += f0 * (a0.x + a0.y);
                lg1 += f1 * (a1.x + a1.y);
                lg2 += f2 * (a2.x + a2.y);
            }
        } else {
            if (t < 192)
                out[n*192 + t] = sm[OFF_FAC + (t >> 6)] * sm[OFF_CAND + t];
        }
    }
}

extern "C" void kernel_launch(void* const* d_in, const int* in_sizes, int n_in,
                              void* d_out, int out_size)
{
    const float* E  = (const float*)d_in[0];  // [N,200,64]
    const float* W  = (const float*)d_in[1];  // [64,64]
    const float* Lg = (const float*)d_in[2];  // [N,3,200]
    const int*   SL = (const int*)d_in[3];    // [N,1]
    float* out = (float*)d_out;               // [N,3,64]

    const int N = in_sizes[3];
    const int smem_bytes = SMEM_FLOATS * (int)sizeof(float);

    cudaFuncSetAttribute(caps_kernel,
                         cudaFuncAttributeMaxDynamicSharedMemorySize, smem_bytes);

    caps_kernel<<<N, 256, smem_bytes>>>(E, W, Lg, SL, out);
}

// round 15
// speedup vs baseline: 1.3082x; 1.3082x over previous
#include <cuda_runtime.h>
#include <cstdint>

#define LSEQ 200
#define LP   68

// ---- smem float offsets ----
#define OFF_MS   0              // A tf32 [200][68], later Ms
#define OFF_BF   13600          // B fragments 8*8*66 = 4224 floats (dead after MMA)
#define OFF_WTSI OFF_BF         // [200][4] = 800   (aliases BF in Phase C)
#define OFF_PART (OFF_BF+800)   // [16][3][64] = 3072
#define OFF_CAND (OFF_BF+3872)  // [192]
#define OFF_FAC  (OFF_BF+4064)  // [4]
#define OFF_SMK  (OFF_BF+4068)  // [64]
// allocation covers the LARGEST region above OFF_BF: BF=4224 > pool=4132
#define SMEM_FLOATS (OFF_BF + 4224)   // 17824 floats = 71296 B -> 3 CTAs/SM (213.9KB)

__device__ __forceinline__ uint32_t to_tf32(float x) {
    uint32_t u;
    asm("cvt.rna.tf32.f32 %0, %1;" : "=r"(u) : "f"(x));
    return u;
}

__device__ __forceinline__ void mma_tf32(float& c0, float& c1, float& c2, float& c3,
                                         uint32_t a0, uint32_t a1, uint32_t a2, uint32_t a3,
                                         uint32_t b0, uint32_t b1) {
    asm volatile("mma.sync.aligned.m16n8k8.row.col.f32.tf32.tf32.f32 "
                 "{%0,%1,%2,%3}, {%4,%5,%6,%7}, {%8,%9}, {%0,%1,%2,%3};"
                 : "+f"(c0), "+f"(c1), "+f"(c2), "+f"(c3)
                 : "r"(a0), "r"(a1), "r"(a2), "r"(a3), "r"(b0), "r"(b1));
}

__device__ __forceinline__ float2 ffma2(float2 a, float2 b, float2 c) {
    float2 r;
    asm("fma.rn.f32x2 %0, %1, %2, %3;"
        : "=l"(reinterpret_cast<unsigned long long&>(r))
        : "l"(reinterpret_cast<unsigned long long&>(a)),
          "l"(reinterpret_cast<unsigned long long&>(b)),
          "l"(reinterpret_cast<unsigned long long&>(c)));
    return r;
}

__global__ __launch_bounds__(256, 3)
void caps_kernel(const float* __restrict__ E,
                 const float* __restrict__ Wg,
                 const float* __restrict__ Lg,
                 const int*   __restrict__ SL,
                 float* __restrict__ out)
{
    extern __shared__ float sm[];
    const int n = blockIdx.x;
    const int t = threadIdx.x;
    const int wid = t >> 5, lane = t & 31;

    // ---- stage B fragments: tile (nb,kb) = 66 floats ----
    {
        const float4* w4 = reinterpret_cast<const float4*>(Wg);
        #pragma unroll 1
        for (int i = 0; i < 4; i++) {
            const int f = t + 256*i;              // f < 1024
            const int d = f >> 4;
            const float4 v = w4[f];
            const float vv[4] = { v.x, v.y, v.z, v.w };
            #pragma unroll
            for (int j = 0; j < 4; j++) {
                const int o = 4*(f & 15) + j;
                const int nb = o >> 3, kb = d >> 3;
                const int ln = ((o & 7) << 2) | (d & 3);
                const int slot = ((d & 7) >> 2);
                sm[OFF_BF + (nb*8 + kb)*66 + ln*2 + slot] =
                    __uint_as_float(to_tf32(vv[j]));
            }
        }
    }

    // ---- stage A row-major [200][68] (tf32), vectorized ----
    {
        const float4* e4 = reinterpret_cast<const float4*>(E + (size_t)n * LSEQ * 64);
        #pragma unroll
        for (int i = 0; i < 13; i++) {
            const int f = t + 256*i;              // f < 3200
            if (f < 3200) {
                const int l = f >> 4, q = f & 15;
                const float4 v = e4[f];
                uint4 u;
                u.x = to_tf32(v.x); u.y = to_tf32(v.y);
                u.z = to_tf32(v.z); u.w = to_tf32(v.w);
                *reinterpret_cast<uint4*>(sm + OFF_MS + l*LP + 4*q) = u;
            }
        }
    }

    // logits in registers: thread t owns position l = t (t < 200)
    float lg0 = 0.f, lg1 = 0.f, lg2 = 0.f;
    if (t < LSEQ) {
        const float* lgp = Lg + n*600 + t;
        lg0 = lgp[0]; lg1 = lgp[200]; lg2 = lgp[400];
    }
    const int sl_raw = SL[n];
    const int sl = (sl_raw < 0) ? 0 : ((sl_raw > LSEQ) ? LSEQ : sl_raw);
    __syncthreads();

    // ---- Phase B mma in TWO m-passes (acc 32 floats -> fits 85 regs, no spill) ----
    // A rows of an m-block are shared by the TWO wn-sibling warps (wid=2wm, 2wm+1).
    // In-place D->A epilogue therefore needs a PAIR barrier (named bar wm+1, 64 thr)
    // between each pass's MMA reads and its epilogue writes. Pass-1 A rows are
    // disjoint from pass-0 D rows, so no cross-pass ordering is needed.
    const int wm = wid >> 1, wn = wid & 1;
    const int mb_base = (wm == 0) ? 0 : (1 + 3*wm);      // 0,4,7,10
    const int mbcnt   = (wm == 0) ? 4 : 3;
    const int r_lo = lane >> 2, c_lo = lane & 3;

    #pragma unroll 1
    for (int pass = 0; pass < 2; pass++) {
        const int pb = mb_base + pass*2;
        const int pcnt = mbcnt - pass*2;                 // pass0: 2, pass1: 1 or 2

        float acc[2][4][4];
        #pragma unroll
        for (int a = 0; a < 2; a++)
            #pragma unroll
            for (int b = 0; b < 4; b++)
                #pragma unroll
                for (int c = 0; c < 4; c++) acc[a][b][c] = 0.f;

        #pragma unroll 1
        for (int kb = 0; kb < 8; kb++) {
            uint32_t bf[4][2];
            #pragma unroll
            for (int nbl = 0; nbl < 4; nbl++) {
                const int nb = wn*4 + nbl;
                const uint2 bv = *reinterpret_cast<const uint2*>(
                    sm + OFF_BF + (nb*8 + kb)*66 + lane*2);
                bf[nbl][0] = bv.x; bf[nbl][1] = bv.y;
            }
            #pragma unroll
            for (int mbl = 0; mbl < 2; mbl++) {
                if (mbl < pcnt) {
                    const int mb = pb + mbl;
                    const float* Ap = sm + OFF_MS + (mb*16 + r_lo)*LP + kb*8 + c_lo;
                    const uint32_t a0 = __float_as_uint(Ap[0]);
                    const uint32_t a1 = __float_as_uint(Ap[8*LP]);
                    const uint32_t a2 = __float_as_uint(Ap[4]);
                    const uint32_t a3 = __float_as_uint(Ap[8*LP + 4]);
                    #pragma unroll
                    for (int nbl = 0; nbl < 4; nbl++)
                        mma_tf32(acc[mbl][nbl][0], acc[mbl][nbl][1],
                                 acc[mbl][nbl][2], acc[mbl][nbl][3],
                                 a0, a1, a2, a3, bf[nbl][0], bf[nbl][1]);
                }
            }
        }

        // pair barrier: sibling must finish reading A(pass) before D(pass) overwrites it
        asm volatile("bar.sync %0, %1;" :: "r"(wm + 1), "r"(64) : "memory");

        // in-place epilogue for this pass's rows
        {
            const int cbase = 2*c_lo;
            #pragma unroll
            for (int mbl = 0; mbl < 2; mbl++) {
                if (mbl < pcnt) {
                    const int mb = pb + mbl;
                    const int r0 = mb*16 + r_lo, r1 = r0 + 8;
                    #pragma unroll
                    for (int nbl = 0; nbl < 4; nbl++) {
                        const int nn = (wn*4 + nbl)*8 + cbase;
                        *reinterpret_cast<float2*>(sm + OFF_MS + r0*LP + nn) =
                            make_float2(acc[mbl][nbl][0], acc[mbl][nbl][1]);
                        if (r1 < LSEQ)
                            *reinterpret_cast<float2*>(sm + OFF_MS + r1*LP + nn) =
                                make_float2(acc[mbl][nbl][2], acc[mbl][nbl][3]);
                    }
                }
            }
        }
    }
    __syncthreads();   // Ms complete; BF becomes Phase-C pool

    // ---- masked-tail constant: SMK[o] = (1/3) * sum_{l>=sl} Ms[l][o] ----
    {
        const int o = t & 63, g = t >> 6;         // 4 l-strided groups
        float s = 0.f;
        #pragma unroll 1
        for (int l = g; l < LSEQ; l += 4)
            if (l >= sl) s += sm[OFF_MS + l*LP + o];
        sm[OFF_PART + g*64 + o] = s;
    }
    __syncthreads();
    if (t < 64) {
        sm[OFF_SMK + t] = (sm[OFF_PART + t] + sm[OFF_PART + 64 + t]
                         + sm[OFF_PART + 128 + t] + sm[OFF_PART + 192 + t]) * (1.f/3.f);
    }
    __syncthreads();

    // ---- Phase C: 3 routing iterations, active positions (l < sl) only ----
    const bool valid = (t < sl);

    #pragma unroll 1
    for (int iter = 0; iter < 3; iter++) {
        if (valid) {
            const float m  = fmaxf(lg0, fmaxf(lg1, lg2));
            const float e0 = __expf(lg0 - m), e1 = __expf(lg1 - m), e2 = __expf(lg2 - m);
            const float inv = __frcp_rn(e0 + e1 + e2);
            *reinterpret_cast<float4*>(sm + OFF_WTSI + 4*t) =
                make_float4(e0*inv, e1*inv, e2*inv, 0.f);
        }
        __syncthreads();

        // candidate partials, load-balanced: thread (o4, lq) covers l = lq + 16j
        {
            const int o4 = t & 15, lq = t >> 4;
            float2 c[3][2];
            #pragma unroll
            for (int k = 0; k < 3; k++) { c[k][0] = make_float2(0.f,0.f); c[k][1] = make_float2(0.f,0.f); }
            #pragma unroll 1
            for (int l = lq; l < sl; l += 16) {
                const float4 m4 = *reinterpret_cast<const float4*>(sm + OFF_MS + l*LP + 4*o4);
                const float4 wv = *reinterpret_cast<const float4*>(sm + OFF_WTSI + 4*l);
                const float2 mlo = make_float2(m4.x, m4.y), mhi = make_float2(m4.z, m4.w);
                c[0][0] = ffma2(make_float2(wv.x, wv.x), mlo, c[0][0]);
                c[0][1] = ffma2(make_float2(wv.x, wv.x), mhi, c[0][1]);
                c[1][0] = ffma2(make_float2(wv.y, wv.y), mlo, c[1][0]);
                c[1][1] = ffma2(make_float2(wv.y, wv.y), mhi, c[1][1]);
                c[2][0] = ffma2(make_float2(wv.z, wv.z), mlo, c[2][0]);
                c[2][1] = ffma2(make_float2(wv.z, wv.z), mhi, c[2][1]);
            }
            #pragma unroll
            for (int k = 0; k < 3; k++)
                *reinterpret_cast<float4*>(sm + OFF_PART + (lq*3 + k)*64 + 4*o4) =
                    make_float4(c[k][0].x, c[k][0].y, c[k][1].x, c[k][1].y);
        }
        __syncthreads();

        // merged reduce + squash-factor: warp k owns capsule k
        if (t < 96) {
            const int k = t >> 5, ln = t & 31;
            float s1 = sm[OFF_SMK + ln], s2 = sm[OFF_SMK + 32 + ln];
            #pragma unroll
            for (int lq = 0; lq < 16; lq++) {
                s1 += sm[OFF_PART + (lq*3 + k)*64 + ln];
                s2 += sm[OFF_PART + (lq*3 + k)*64 + 32 + ln];
            }
            sm[OFF_CAND + k*64 + ln]      = s1;
            sm[OFF_CAND + k*64 + 32 + ln] = s2;
            float sq = s1*s1 + s2*s2;
            #pragma unroll
            for (int off = 16; off; off >>= 1) sq += __shfl_xor_sync(0xffffffffu, sq, off);
            if (ln == 0) sm[OFF_FAC + k] = sq / ((1.f + sq) * sqrtf(sq + 1e-8f));
        }
        __syncthreads();

        if (iter < 2) {
            if (valid) {                           // masked logits never used again
                const float4* ml = reinterpret_cast<const float4*>(sm + OFF_MS + t*LP);
                const float4* c0 = reinterpret_cast<const float4*>(sm + OFF_CAND);
                const float4* c1 = reinterpret_cast<const float4*>(sm + OFF_CAND + 64);
                const float4* c2 = reinterpret_cast<const float4*>(sm + OFF_CAND + 128);
                float2 a0 = make_float2(0.f,0.f), a1 = make_float2(0.f,0.f), a2 = make_float2(0.f,0.f);
                #pragma unroll 4
                for (int q = 0; q < 16; q++) {
                    const float4 m = ml[q];
                    const float2 mlo = make_float2(m.x, m.y), mhi = make_float2(m.z, m.w);
                    const float4 x0 = c0[q], x1 = c1[q], x2 = c2[q];
                    a0 = ffma2(mlo, make_float2(x0.x, x0.y), a0);
                    a0 = ffma2(mhi, make_float2(x0.z, x0.w), a0);
                    a1 = ffma2(mlo, make_float2(x1.x, x1.y), a1);
                    a1 = ffma2(mhi, make_float2(x1.z, x1.w), a1);
                    a2 = ffma2(mlo, make_float2(x2.x, x2.y), a2);
                    a2 = ffma2(mhi, make_float2(x2.z, x2.w), a2);
                }
                const float f0 = sm[OFF_FAC], f1 = sm[OFF_FAC + 1], f2 = sm[OFF_FAC + 2];
                lg0 += f0 * (a0.x + a0.y);
                lg1 += f1 * (a1.x + a1.y);
                lg2 += f2 * (a2.x + a2.y);
            }
        } else {
            if (t < 192)
                out[n*192 + t] = sm[OFF_FAC + (t >> 6)] * sm[OFF_CAND + t];
        }
    }
}

extern "C" void kernel_launch(void* const* d_in, const int* in_sizes, int n_in,
                              void* d_out, int out_size)
{
    const float* E  = (const float*)d_in[0];  // [N,200,64]
    const float* W  = (const float*)d_in[1];  // [64,64]
    const float* Lg = (const float*)d_in[2];  // [N,3,200]
    const int*   SL = (const int*)d_in[3];    // [N,1]
    float* out = (float*)d_out;               // [N,3,64]

    const int N = in_sizes[3];
    const int smem_bytes = SMEM_FLOATS * (int)sizeof(float);

    cudaFuncSetAttribute(caps_kernel,
                         cudaFuncAttributeMaxDynamicSharedMemorySize, smem_bytes);

    caps_kernel<<<N, 256, smem_bytes>>>(E, W, Lg, SL, out);
}

// round 16
// speedup vs baseline: 1.3817x; 1.0562x over previous
#include <cuda_runtime.h>
#include <cstdint>

#define LSEQ 200
#define LP   68

// ---- smem float offsets ----
#define OFF_MS   0              // A tf32 [200][68], later Ms
#define OFF_BF   13600          // B fragments 8*8*66 = 4224 floats (dead after MMA)
#define OFF_WTSI OFF_BF         // [200][4] = 800   (aliases BF in Phase C)
#define OFF_PART (OFF_BF+800)   // [16][3][64] = 3072
#define OFF_CAND (OFF_BF+3872)  // [192]
#define OFF_FAC  (OFF_BF+4064)  // [4]
#define OFF_SMK  (OFF_BF+4068)  // [64]
// allocation covers the LARGEST region above OFF_BF: BF=4224 > pool=4132
#define SMEM_FLOATS (OFF_BF + 4224)   // 17824 floats = 71296 B -> 3 CTAs/SM

__device__ __forceinline__ uint32_t to_tf32(float x) {
    uint32_t u;
    asm("cvt.rna.tf32.f32 %0, %1;" : "=r"(u) : "f"(x));
    return u;
}

__device__ __forceinline__ void mma_tf32(float& c0, float& c1, float& c2, float& c3,
                                         uint32_t a0, uint32_t a1, uint32_t a2, uint32_t a3,
                                         uint32_t b0, uint32_t b1) {
    asm volatile("mma.sync.aligned.m16n8k8.row.col.f32.tf32.tf32.f32 "
                 "{%0,%1,%2,%3}, {%4,%5,%6,%7}, {%8,%9}, {%0,%1,%2,%3};"
                 : "+f"(c0), "+f"(c1), "+f"(c2), "+f"(c3)
                 : "r"(a0), "r"(a1), "r"(a2), "r"(a3), "r"(b0), "r"(b1));
}

__device__ __forceinline__ float2 ffma2(float2 a, float2 b, float2 c) {
    float2 r;
    asm("fma.rn.f32x2 %0, %1, %2, %3;"
        : "=l"(reinterpret_cast<unsigned long long&>(r))
        : "l"(reinterpret_cast<unsigned long long&>(a)),
          "l"(reinterpret_cast<unsigned long long&>(b)),
          "l"(reinterpret_cast<unsigned long long&>(c)));
    return r;
}

__global__ __launch_bounds__(256, 3)
void caps_kernel(const float* __restrict__ E,
                 const float* __restrict__ Wg,
                 const float* __restrict__ Lg,
                 const int*   __restrict__ SL,
                 float* __restrict__ out)
{
    extern __shared__ float sm[];
    const int n = blockIdx.x;
    const int t = threadIdx.x;
    const int wid = t >> 5, lane = t & 31;

    // ---- stage B fragments: tile (nb,kb) = 66 floats ----
    {
        const float4* w4 = reinterpret_cast<const float4*>(Wg);
        #pragma unroll 1
        for (int i = 0; i < 4; i++) {
            const int f = t + 256*i;              // f < 1024
            const int d = f >> 4;
            const float4 v = w4[f];
            const float vv[4] = { v.x, v.y, v.z, v.w };
            #pragma unroll
            for (int j = 0; j < 4; j++) {
                const int o = 4*(f & 15) + j;
                const int nb = o >> 3, kb = d >> 3;
                const int ln = ((o & 7) << 2) | (d & 3);
                const int slot = ((d & 7) >> 2);
                sm[OFF_BF + (nb*8 + kb)*66 + ln*2 + slot] =
                    __uint_as_float(to_tf32(vv[j]));
            }
        }
    }

    // ---- stage A row-major [200][68] (tf32), vectorized ----
    {
        const float4* e4 = reinterpret_cast<const float4*>(E + (size_t)n * LSEQ * 64);
        #pragma unroll
        for (int i = 0; i < 13; i++) {
            const int f = t + 256*i;              // f < 3200
            if (f < 3200) {
                const int l = f >> 4, q = f & 15;
                const float4 v = e4[f];
                uint4 u;
                u.x = to_tf32(v.x); u.y = to_tf32(v.y);
                u.z = to_tf32(v.z); u.w = to_tf32(v.w);
                *reinterpret_cast<uint4*>(sm + OFF_MS + l*LP + 4*q) = u;
            }
        }
    }

    // logits in registers: thread t owns position l = t (t < 200)
    float lg0 = 0.f, lg1 = 0.f, lg2 = 0.f;
    if (t < LSEQ) {
        const float* lgp = Lg + n*600 + t;
        lg0 = lgp[0]; lg1 = lgp[200]; lg2 = lgp[400];
    }
    const int sl_raw = SL[n];
    const int sl = (sl_raw < 0) ? 0 : ((sl_raw > LSEQ) ? LSEQ : sl_raw);
    __syncthreads();

    // ---- Phase B mma in TWO m-passes (acc 32 floats, <=85 regs) ----
    const int wm = wid >> 1, wn = wid & 1;
    const int mb_base = (wm == 0) ? 0 : (1 + 3*wm);      // 0,4,7,10
    const int mbcnt   = (wm == 0) ? 4 : 3;
    const int r_lo = lane >> 2, c_lo = lane & 3;

    #pragma unroll 1
    for (int pass = 0; pass < 2; pass++) {
        const int pb = mb_base + pass*2;
        const int pcnt = mbcnt - pass*2;                 // pass0: 2, pass1: 1 or 2

        float acc[2][4][4];
        #pragma unroll
        for (int a = 0; a < 2; a++)
            #pragma unroll
            for (int b = 0; b < 4; b++)
                #pragma unroll
                for (int c = 0; c < 4; c++) acc[a][b][c] = 0.f;

        #pragma unroll 2
        for (int kb = 0; kb < 8; kb++) {
            uint32_t bf[4][2];
            #pragma unroll
            for (int nbl = 0; nbl < 4; nbl++) {
                const int nb = wn*4 + nbl;
                const uint2 bv = *reinterpret_cast<const uint2*>(
                    sm + OFF_BF + (nb*8 + kb)*66 + lane*2);
                bf[nbl][0] = bv.x; bf[nbl][1] = bv.y;
            }
            #pragma unroll
            for (int mbl = 0; mbl < 2; mbl++) {
                if (mbl < pcnt) {
                    const int mb = pb + mbl;
                    const float* Ap = sm + OFF_MS + (mb*16 + r_lo)*LP + kb*8 + c_lo;
                    const uint32_t a0 = __float_as_uint(Ap[0]);
                    const uint32_t a1 = __float_as_uint(Ap[8*LP]);
                    const uint32_t a2 = __float_as_uint(Ap[4]);
                    const uint32_t a3 = __float_as_uint(Ap[8*LP + 4]);
                    #pragma unroll
                    for (int nbl = 0; nbl < 4; nbl++)
                        mma_tf32(acc[mbl][nbl][0], acc[mbl][nbl][1],
                                 acc[mbl][nbl][2], acc[mbl][nbl][3],
                                 a0, a1, a2, a3, bf[nbl][0], bf[nbl][1]);
                }
            }
        }

        // pair barrier: sibling must finish reading A(pass) before D(pass) overwrites it
        asm volatile("bar.sync %0, %1;" :: "r"(wm + 1), "r"(64) : "memory");

        // in-place epilogue for this pass's rows
        {
            const int cbase = 2*c_lo;
            #pragma unroll
            for (int mbl = 0; mbl < 2; mbl++) {
                if (mbl < pcnt) {
                    const int mb = pb + mbl;
                    const int r0 = mb*16 + r_lo, r1 = r0 + 8;
                    #pragma unroll
                    for (int nbl = 0; nbl < 4; nbl++) {
                        const int nn = (wn*4 + nbl)*8 + cbase;
                        *reinterpret_cast<float2*>(sm + OFF_MS + r0*LP + nn) =
                            make_float2(acc[mbl][nbl][0], acc[mbl][nbl][1]);
                        if (r1 < LSEQ)
                            *reinterpret_cast<float2*>(sm + OFF_MS + r1*LP + nn) =
                                make_float2(acc[mbl][nbl][2], acc[mbl][nbl][3]);
                    }
                }
            }
        }
    }
    __syncthreads();   // Ms complete; BF becomes Phase-C pool

    // ---- masked-tail constant: SMK[o] = (1/3) * sum_{l>=sl} Ms[l][o] ----
    {
        const int o = t & 63, g = t >> 6;         // 4 l-strided groups
        float s = 0.f;
        #pragma unroll 2
        for (int l = g; l < LSEQ; l += 4)
            if (l >= sl) s += sm[OFF_MS + l*LP + o];
        sm[OFF_PART + g*64 + o] = s;
    }
    __syncthreads();
    if (t < 64) {
        sm[OFF_SMK + t] = (sm[OFF_PART + t] + sm[OFF_PART + 64 + t]
                         + sm[OFF_PART + 128 + t] + sm[OFF_PART + 192 + t]) * (1.f/3.f);
    }
    __syncthreads();

    // ---- Phase C: 3 routing iterations, active positions (l < sl) only ----
    const bool valid = (t < sl);

    #pragma unroll 1
    for (int iter = 0; iter < 3; iter++) {
        if (valid) {
            const float m  = fmaxf(lg0, fmaxf(lg1, lg2));
            const float e0 = __expf(lg0 - m), e1 = __expf(lg1 - m), e2 = __expf(lg2 - m);
            const float inv = __frcp_rn(e0 + e1 + e2);
            *reinterpret_cast<float4*>(sm + OFF_WTSI + 4*t) =
                make_float4(e0*inv, e1*inv, e2*inv, 0.f);
        }
        __syncthreads();

        // candidate partials, load-balanced + unroll 2 (two independent acc sets)
        {
            const int o4 = t & 15, lq = t >> 4;
            float2 cA[3][2], cB[3][2];
            #pragma unroll
            for (int k = 0; k < 3; k++) {
                cA[k][0] = make_float2(0.f,0.f); cA[k][1] = make_float2(0.f,0.f);
                cB[k][0] = make_float2(0.f,0.f); cB[k][1] = make_float2(0.f,0.f);
            }
            int l = lq;
            #pragma unroll 1
            for (; l + 16 < sl; l += 32) {
                const float4 m4a = *reinterpret_cast<const float4*>(sm + OFF_MS + l*LP + 4*o4);
                const float4 wva = *reinterpret_cast<const float4*>(sm + OFF_WTSI + 4*l);
                const float4 m4b = *reinterpret_cast<const float4*>(sm + OFF_MS + (l+16)*LP + 4*o4);
                const float4 wvb = *reinterpret_cast<const float4*>(sm + OFF_WTSI + 4*(l+16));
                const float2 mloA = make_float2(m4a.x, m4a.y), mhiA = make_float2(m4a.z, m4a.w);
                const float2 mloB = make_float2(m4b.x, m4b.y), mhiB = make_float2(m4b.z, m4b.w);
                cA[0][0] = ffma2(make_float2(wva.x, wva.x), mloA, cA[0][0]);
                cA[0][1] = ffma2(make_float2(wva.x, wva.x), mhiA, cA[0][1]);
                cA[1][0] = ffma2(make_float2(wva.y, wva.y), mloA, cA[1][0]);
                cA[1][1] = ffma2(make_float2(wva.y, wva.y), mhiA, cA[1][1]);
                cA[2][0] = ffma2(make_float2(wva.z, wva.z), mloA, cA[2][0]);
                cA[2][1] = ffma2(make_float2(wva.z, wva.z), mhiA, cA[2][1]);
                cB[0][0] = ffma2(make_float2(wvb.x, wvb.x), mloB, cB[0][0]);
                cB[0][1] = ffma2(make_float2(wvb.x, wvb.x), mhiB, cB[0][1]);
                cB[1][0] = ffma2(make_float2(wvb.y, wvb.y), mloB, cB[1][0]);
                cB[1][1] = ffma2(make_float2(wvb.y, wvb.y), mhiB, cB[1][1]);
                cB[2][0] = ffma2(make_float2(wvb.z, wvb.z), mloB, cB[2][0]);
                cB[2][1] = ffma2(make_float2(wvb.z, wvb.z), mhiB, cB[2][1]);
            }
            if (l < sl) {
                const float4 m4 = *reinterpret_cast<const float4*>(sm + OFF_MS + l*LP + 4*o4);
                const float4 wv = *reinterpret_cast<const float4*>(sm + OFF_WTSI + 4*l);
                const float2 mlo = make_float2(m4.x, m4.y), mhi = make_float2(m4.z, m4.w);
                cA[0][0] = ffma2(make_float2(wv.x, wv.x), mlo, cA[0][0]);
                cA[0][1] = ffma2(make_float2(wv.x, wv.x), mhi, cA[0][1]);
                cA[1][0] = ffma2(make_float2(wv.y, wv.y), mlo, cA[1][0]);
                cA[1][1] = ffma2(make_float2(wv.y, wv.y), mhi, cA[1][1]);
                cA[2][0] = ffma2(make_float2(wv.z, wv.z), mlo, cA[2][0]);
                cA[2][1] = ffma2(make_float2(wv.z, wv.z), mhi, cA[2][1]);
            }
            #pragma unroll
            for (int k = 0; k < 3; k++) {
                const float2 s0 = make_float2(cA[k][0].x + cB[k][0].x, cA[k][0].y + cB[k][0].y);
                const float2 s1 = make_float2(cA[k][1].x + cB[k][1].x, cA[k][1].y + cB[k][1].y);
                *reinterpret_cast<float4*>(sm + OFF_PART + (lq*3 + k)*64 + 4*o4) =
                    make_float4(s0.x, s0.y, s1.x, s1.y);
            }
        }
        __syncthreads();

        // merged reduce + squash-factor: warp k owns capsule k
        if (t < 96) {
            const int k = t >> 5, ln = t & 31;
            float s1 = sm[OFF_SMK + ln], s2 = sm[OFF_SMK + 32 + ln];
            #pragma unroll
            for (int lq = 0; lq < 16; lq++) {
                s1 += sm[OFF_PART + (lq*3 + k)*64 + ln];
                s2 += sm[OFF_PART + (lq*3 + k)*64 + 32 + ln];
            }
            sm[OFF_CAND + k*64 + ln]      = s1;
            sm[OFF_CAND + k*64 + 32 + ln] = s2;
            float sq = s1*s1 + s2*s2;
            #pragma unroll
            for (int off = 16; off; off >>= 1) sq += __shfl_xor_sync(0xffffffffu, sq, off);
            if (ln == 0) sm[OFF_FAC + k] = sq / ((1.f + sq) * sqrtf(sq + 1e-8f));
        }
        __syncthreads();

        if (iter < 2) {
            if (valid) {
                const float4* ml = reinterpret_cast<const float4*>(sm + OFF_MS + t*LP);
                const float4* c0 = reinterpret_cast<const float4*>(sm + OFF_CAND);
                const float4* c1 = reinterpret_cast<const float4*>(sm + OFF_CAND + 64);
                const float4* c2 = reinterpret_cast<const float4*>(sm + OFF_CAND + 128);
                float2 a0 = make_float2(0.f,0.f), a1 = make_float2(0.f,0.f), a2 = make_float2(0.f,0.f);
                #pragma unroll 4
                for (int q = 0; q < 16; q++) {
                    const float4 m = ml[q];
                    const float2 mlo = make_float2(m.x, m.y), mhi = make_float2(m.z, m.w);
                    const float4 x0 = c0[q], x1 = c1[q], x2 = c2[q];
                    a0 = ffma2(mlo, make_float2(x0.x, x0.y), a0);
                    a0 = ffma2(mhi, make_float2(x0.z, x0.w), a0);
                    a1 = ffma2(mlo, make_float2(x1.x, x1.y), a1);
                    a1 = ffma2(mhi, make_float2(x1.z, x1.w), a1);
                    a2 = ffma2(mlo, make_float2(x2.x, x2.y), a2);
                    a2 = ffma2(mhi, make_float2(x2.z, x2.w), a2);
                }
                const float f0 = sm[OFF_FAC], f1 = sm[OFF_FAC + 1], f2 = sm[OFF_FAC + 2];
                lg0 += f0 * (a0.x + a0.y);
                lg1 += f1 * (a1.x + a1.y);
                lg2 += f2 * (a2.x + a2.y);
            }
        } else {
            if (t < 192)
                out[n*192 + t] = sm[OFF_FAC + (t >> 6)] * sm[OFF_CAND + t];
        }
    }
}

extern "C" void kernel_launch(void* const* d_in, const int* in_sizes, int n_in,
                              void* d_out, int out_size)
{
    const float* E  = (const float*)d_in[0];  // [N,200,64]
    const float* W  = (const float*)d_in[1];  // [64,64]
    const float* Lg = (const float*)d_in[2];  // [N,3,200]
    const int*   SL = (const int*)d_in[3];    // [N,1]
    float* out = (float*)d_out;               // [N,3,64]

    const int N = in_sizes[3];
    const int smem_bytes = SMEM_FLOATS * (int)sizeof(float);

    cudaFuncSetAttribute(caps_kernel,
                         cudaFuncAttributeMaxDynamicSharedMemorySize, smem_bytes);

    caps_kernel<<<N, 256, smem_bytes>>>(E, W, Lg, SL, out);
}

// round 17
// speedup vs baseline: 1.5182x; 1.0988x over previous
#include <cuda_runtime.h>
#include <cstdint>

#define LSEQ 200
#define LP   68

// ---- smem float offsets ----
#define OFF_MS   0               // A tf32 [200][68], later Ms
#define OFF_BF   13600           // B fragments 8*8*66 = 4224 floats
#define OFF_WTSI OFF_BF          // [200][4] (aliases BF in Phase C; BF dead after GEMV)
#define OFF_PART (OFF_BF+800)    // [16][3][64] = 3072
#define OFF_CAND (OFF_BF+3872)   // [192]
#define OFF_FAC  (OFF_BF+4064)   // [4]
#define OFF_ES   (OFF_BF+4224)   // [256][4] esum partials = 1024  (17824)
#define OFF_ESUM (OFF_ES+1024)   // [64]                            (18848)
#define OFF_SMK  (OFF_ESUM+64)   // [64]                            (18912)
#define SMEM_FLOATS (OFF_SMK+64) // 18976 floats = 75904 B -> 3 CTAs/SM

__device__ __forceinline__ uint32_t to_tf32(float x) {
    uint32_t u;
    asm("cvt.rna.tf32.f32 %0, %1;" : "=r"(u) : "f"(x));
    return u;
}

__device__ __forceinline__ void mma_tf32(float& c0, float& c1, float& c2, float& c3,
                                         uint32_t a0, uint32_t a1, uint32_t a2, uint32_t a3,
                                         uint32_t b0, uint32_t b1) {
    asm volatile("mma.sync.aligned.m16n8k8.row.col.f32.tf32.tf32.f32 "
                 "{%0,%1,%2,%3}, {%4,%5,%6,%7}, {%8,%9}, {%0,%1,%2,%3};"
                 : "+f"(c0), "+f"(c1), "+f"(c2), "+f"(c3)
                 : "r"(a0), "r"(a1), "r"(a2), "r"(a3), "r"(b0), "r"(b1));
}

__device__ __forceinline__ float2 ffma2(float2 a, float2 b, float2 c) {
    float2 r;
    asm("fma.rn.f32x2 %0, %1, %2, %3;"
        : "=l"(reinterpret_cast<unsigned long long&>(r))
        : "l"(reinterpret_cast<unsigned long long&>(a)),
          "l"(reinterpret_cast<unsigned long long&>(b)),
          "l"(reinterpret_cast<unsigned long long&>(c)));
    return r;
}

__global__ __launch_bounds__(256, 3)
void caps_kernel(const float* __restrict__ E,
                 const float* __restrict__ Wg,
                 const float* __restrict__ Lg,
                 const int*   __restrict__ SL,
                 float* __restrict__ out)
{
    extern __shared__ float sm[];
    const int n = blockIdx.x;
    const int t = threadIdx.x;
    const int wid = t >> 5, lane = t & 31;

    const int sl_raw = SL[n];
    const int sl = (sl_raw < 0) ? 0 : ((sl_raw > LSEQ) ? LSEQ : sl_raw);
    const int n_active_mb = (sl + 15) >> 4;        // m-blocks with any row < sl

    // ---- stage B fragments: tile (nb,kb) = 66 floats ----
    {
        const float4* w4 = reinterpret_cast<const float4*>(Wg);
        #pragma unroll 1
        for (int i = 0; i < 4; i++) {
            const int f = t + 256*i;              // f < 1024
            const int d = f >> 4;
            const float4 v = w4[f];
            const float vv[4] = { v.x, v.y, v.z, v.w };
            #pragma unroll
            for (int j = 0; j < 4; j++) {
                const int o = 4*(f & 15) + j;
                const int nb = o >> 3, kb = d >> 3;
                const int ln = ((o & 7) << 2) | (d & 3);
                const int slot = ((d & 7) >> 2);
                sm[OFF_BF + (nb*8 + kb)*66 + ln*2 + slot] =
                    __uint_as_float(to_tf32(vv[j]));
            }
        }
    }

    // ---- stage A rows l<sl as tf32 [200][68]; accumulate raw-E sum for l>=sl ----
    {
        const float4* e4 = reinterpret_cast<const float4*>(E + (size_t)n * LSEQ * 64);
        float4 es = make_float4(0.f, 0.f, 0.f, 0.f);   // d-slice 4*(t&15)..+3
        #pragma unroll
        for (int i = 0; i < 13; i++) {
            const int f = t + 256*i;              // f < 3200
            if (f < 3200) {
                const int l = f >> 4, q = f & 15;
                const float4 v = e4[f];
                if (l < sl) {
                    uint4 u;
                    u.x = to_tf32(v.x); u.y = to_tf32(v.y);
                    u.z = to_tf32(v.z); u.w = to_tf32(v.w);
                    *reinterpret_cast<uint4*>(sm + OFF_MS + l*LP + 4*q) = u;
                } else {
                    es.x += v.x; es.y += v.y; es.z += v.z; es.w += v.w;
                }
            }
        }
        *reinterpret_cast<float4*>(sm + OFF_ES + 4*t) = es;
    }

    // logits in registers: thread t owns position l = t (t < 200)
    float lg0 = 0.f, lg1 = 0.f, lg2 = 0.f;
    if (t < LSEQ) {
        const float* lgp = Lg + n*600 + t;
        lg0 = lgp[0]; lg1 = lgp[200]; lg2 = lgp[400];
    }
    __syncthreads();

    // ---- Phase B mma in TWO m-passes, only active m-blocks (mb < n_active_mb) ----
    const int wm = wid >> 1, wn = wid & 1;
    const int mb_base = (wm == 0) ? 0 : (1 + 3*wm);      // 0,4,7,10
    const int mbcnt   = (wm == 0) ? 4 : 3;
    const int r_lo = lane >> 2, c_lo = lane & 3;

    #pragma unroll 1
    for (int pass = 0; pass < 2; pass++) {
        const int pb = mb_base + pass*2;
        const int pcnt = mbcnt - pass*2;                 // pass0: 2, pass1: 1 or 2
        const bool any = (pcnt > 0) && (pb < n_active_mb);

        float acc[2][4][4];
        #pragma unroll
        for (int a = 0; a < 2; a++)
            #pragma unroll
            for (int b = 0; b < 4; b++)
                #pragma unroll
                for (int c = 0; c < 4; c++) acc[a][b][c] = 0.f;

        if (any) {
            #pragma unroll 2
            for (int kb = 0; kb < 8; kb++) {
                uint32_t bf[4][2];
                #pragma unroll
                for (int nbl = 0; nbl < 4; nbl++) {
                    const int nb = wn*4 + nbl;
                    const uint2 bv = *reinterpret_cast<const uint2*>(
                        sm + OFF_BF + (nb*8 + kb)*66 + lane*2);
                    bf[nbl][0] = bv.x; bf[nbl][1] = bv.y;
                }
                #pragma unroll
                for (int mbl = 0; mbl < 2; mbl++) {
                    if (mbl < pcnt && (pb + mbl) < n_active_mb) {
                        const int mb = pb + mbl;
                        const float* Ap = sm + OFF_MS + (mb*16 + r_lo)*LP + kb*8 + c_lo;
                        const uint32_t a0 = __float_as_uint(Ap[0]);
                        const uint32_t a1 = __float_as_uint(Ap[8*LP]);
                        const uint32_t a2 = __float_as_uint(Ap[4]);
                        const uint32_t a3 = __float_as_uint(Ap[8*LP + 4]);
                        #pragma unroll
                        for (int nbl = 0; nbl < 4; nbl++)
                            mma_tf32(acc[mbl][nbl][0], acc[mbl][nbl][1],
                                     acc[mbl][nbl][2], acc[mbl][nbl][3],
                                     a0, a1, a2, a3, bf[nbl][0], bf[nbl][1]);
                    }
                }
            }
        }

        // pair barrier: sibling must finish reading A(pass) before D(pass) overwrites
        asm volatile("bar.sync %0, %1;" :: "r"(wm + 1), "r"(64) : "memory");

        if (any) {
            const int cbase = 2*c_lo;
            #pragma unroll
            for (int mbl = 0; mbl < 2; mbl++) {
                if (mbl < pcnt && (pb + mbl) < n_active_mb) {
                    const int mb = pb + mbl;
                    const int r0 = mb*16 + r_lo, r1 = r0 + 8;
                    #pragma unroll
                    for (int nbl = 0; nbl < 4; nbl++) {
                        const int nn = (wn*4 + nbl)*8 + cbase;
                        *reinterpret_cast<float2*>(sm + OFF_MS + r0*LP + nn) =
                            make_float2(acc[mbl][nbl][0], acc[mbl][nbl][1]);
                        if (r1 < LSEQ)
                            *reinterpret_cast<float2*>(sm + OFF_MS + r1*LP + nn) =
                                make_float2(acc[mbl][nbl][2], acc[mbl][nbl][3]);
                    }
                }
            }
        }
    }
    __syncthreads();   // Ms(active rows) complete; ES partials visible

    // ---- esum reduce: esum[d] = sum over 16 thread-groups ----
    if (t < 64) {
        float s = 0.f;
        #pragma unroll
        for (int g = 0; g < 16; g++) s += sm[OFF_ES + g*64 + t];
        sm[OFF_ESUM + t] = s;
    }
    __syncthreads();

    // ---- SMK[o] = (1/3) * sum_d esum[d] * W_tf32[d][o]  (read W from BF fragments) ----
    if (t < 64) {
        const int nb = t >> 3, ol = t & 7;
        float acc = 0.f;
        #pragma unroll
        for (int kb = 0; kb < 8; kb++) {
            const int base = OFF_BF + (nb*8 + kb)*66;
            #pragma unroll
            for (int s2 = 0; s2 < 8; s2++) {
                const float wv = sm[base + ((ol << 2) | (s2 & 3))*2 + (s2 >> 2)];
                acc = fmaf(sm[OFF_ESUM + kb*8 + s2], wv, acc);
            }
        }
        sm[OFF_SMK + t] = acc * (1.f/3.f);
    }
    __syncthreads();   // BF now dead -> pool (WTSI/PART/CAND/FAC) free

    // ---- Phase C: 3 routing iterations, active positions (l < sl) only ----
    const bool valid = (t < sl);

    #pragma unroll 1
    for (int iter = 0; iter < 3; iter++) {
        if (valid) {
            const float m  = fmaxf(lg0, fmaxf(lg1, lg2));
            const float e0 = __expf(lg0 - m), e1 = __expf(lg1 - m), e2 = __expf(lg2 - m);
            const float inv = __frcp_rn(e0 + e1 + e2);
            *reinterpret_cast<float4*>(sm + OFF_WTSI + 4*t) =
                make_float4(e0*inv, e1*inv, e2*inv, 0.f);
        }
        __syncthreads();

        // candidate partials, load-balanced + unroll 2
        {
            const int o4 = t & 15, lq = t >> 4;
            float2 cA[3][2], cB[3][2];
            #pragma unroll
            for (int k = 0; k < 3; k++) {
                cA[k][0] = make_float2(0.f,0.f); cA[k][1] = make_float2(0.f,0.f);
                cB[k][0] = make_float2(0.f,0.f); cB[k][1] = make_float2(0.f,0.f);
            }
            int l = lq;
            #pragma unroll 1
            for (; l + 16 < sl; l += 32) {
                const float4 m4a = *reinterpret_cast<const float4*>(sm + OFF_MS + l*LP + 4*o4);
                const float4 wva = *reinterpret_cast<const float4*>(sm + OFF_WTSI + 4*l);
                const float4 m4b = *reinterpret_cast<const float4*>(sm + OFF_MS + (l+16)*LP + 4*o4);
                const float4 wvb = *reinterpret_cast<const float4*>(sm + OFF_WTSI + 4*(l+16));
                const float2 mloA = make_float2(m4a.x, m4a.y), mhiA = make_float2(m4a.z, m4a.w);
                const float2 mloB = make_float2(m4b.x, m4b.y), mhiB = make_float2(m4b.z, m4b.w);
                cA[0][0] = ffma2(make_float2(wva.x, wva.x), mloA, cA[0][0]);
                cA[0][1] = ffma2(make_float2(wva.x, wva.x), mhiA, cA[0][1]);
                cA[1][0] = ffma2(make_float2(wva.y, wva.y), mloA, cA[1][0]);
                cA[1][1] = ffma2(make_float2(wva.y, wva.y), mhiA, cA[1][1]);
                cA[2][0] = ffma2(make_float2(wva.z, wva.z), mloA, cA[2][0]);
                cA[2][1] = ffma2(make_float2(wva.z, wva.z), mhiA, cA[2][1]);
                cB[0][0] = ffma2(make_float2(wvb.x, wvb.x), mloB, cB[0][0]);
                cB[0][1] = ffma2(make_float2(wvb.x, wvb.x), mhiB, cB[0][1]);
                cB[1][0] = ffma2(make_float2(wvb.y, wvb.y), mloB, cB[1][0]);
                cB[1][1] = ffma2(make_float2(wvb.y, wvb.y), mhiB, cB[1][1]);
                cB[2][0] = ffma2(make_float2(wvb.z, wvb.z), mloB, cB[2][0]);
                cB[2][1] = ffma2(make_float2(wvb.z, wvb.z), mhiB, cB[2][1]);
            }
            if (l < sl) {
                const float4 m4 = *reinterpret_cast<const float4*>(sm + OFF_MS + l*LP + 4*o4);
                const float4 wv = *reinterpret_cast<const float4*>(sm + OFF_WTSI + 4*l);
                const float2 mlo = make_float2(m4.x, m4.y), mhi = make_float2(m4.z, m4.w);
                cA[0][0] = ffma2(make_float2(wv.x, wv.x), mlo, cA[0][0]);
                cA[0][1] = ffma2(make_float2(wv.x, wv.x), mhi, cA[0][1]);
                cA[1][0] = ffma2(make_float2(wv.y, wv.y), mlo, cA[1][0]);
                cA[1][1] = ffma2(make_float2(wv.y, wv.y), mhi, cA[1][1]);
                cA[2][0] = ffma2(make_float2(wv.z, wv.z), mlo, cA[2][0]);
                cA[2][1] = ffma2(make_float2(wv.z, wv.z), mhi, cA[2][1]);
            }
            #pragma unroll
            for (int k = 0; k < 3; k++) {
                const float2 s0 = make_float2(cA[k][0].x + cB[k][0].x, cA[k][0].y + cB[k][0].y);
                const float2 s1 = make_float2(cA[k][1].x + cB[k][1].x, cA[k][1].y + cB[k][1].y);
                *reinterpret_cast<float4*>(sm + OFF_PART + (lq*3 + k)*64 + 4*o4) =
                    make_float4(s0.x, s0.y, s1.x, s1.y);
            }
        }
        __syncthreads();

        // merged reduce + squash-factor: warp k owns capsule k
        if (t < 96) {
            const int k = t >> 5, ln = t & 31;
            float s1 = sm[OFF_SMK + ln], s2 = sm[OFF_SMK + 32 + ln];
            #pragma unroll
            for (int lq = 0; lq < 16; lq++) {
                s1 += sm[OFF_PART + (lq*3 + k)*64 + ln];
                s2 += sm[OFF_PART + (lq*3 + k)*64 + 32 + ln];
            }
            sm[OFF_CAND + k*64 + ln]      = s1;
            sm[OFF_CAND + k*64 + 32 + ln] = s2;
            float sq = s1*s1 + s2*s2;
            #pragma unroll
            for (int off = 16; off; off >>= 1) sq += __shfl_xor_sync(0xffffffffu, sq, off);
            if (ln == 0) sm[OFF_FAC + k] = sq / ((1.f + sq) * sqrtf(sq + 1e-8f));
        }
        __syncthreads();

        if (iter < 2) {
            if (valid) {
                const float4* ml = reinterpret_cast<const float4*>(sm + OFF_MS + t*LP);
                const float4* c0 = reinterpret_cast<const float4*>(sm + OFF_CAND);
                const float4* c1 = reinterpret_cast<const float4*>(sm + OFF_CAND + 64);
                const float4* c2 = reinterpret_cast<const float4*>(sm + OFF_CAND + 128);
                float2 a0 = make_float2(0.f,0.f), a1 = make_float2(0.f,0.f), a2 = make_float2(0.f,0.f);
                #pragma unroll 4
                for (int q = 0; q < 16; q++) {
                    const float4 m = ml[q];
                    const float2 mlo = make_float2(m.x, m.y), mhi = make_float2(m.z, m.w);
                    const float4 x0 = c0[q], x1 = c1[q], x2 = c2[q];
                    a0 = ffma2(mlo, make_float2(x0.x, x0.y), a0);
                    a0 = ffma2(mhi, make_float2(x0.z, x0.w), a0);
                    a1 = ffma2(mlo, make_float2(x1.x, x1.y), a1);
                    a1 = ffma2(mhi, make_float2(x1.z, x1.w), a1);
                    a2 = ffma2(mlo, make_float2(x2.x, x2.y), a2);
                    a2 = ffma2(mhi, make_float2(x2.z, x2.w), a2);
                }
                const float f0 = sm[OFF_FAC], f1 = sm[OFF_FAC + 1], f2 = sm[OFF_FAC + 2];
                lg0 += f0 * (a0.x + a0.y);
                lg1 += f1 * (a1.x + a1.y);
                lg2 += f2 * (a2.x + a2.y);
            }
        } else {
            if (t < 192)
                out[n*192 + t] = sm[OFF_FAC + (t >> 6)] * sm[OFF_CAND + t];
        }
    }
}

extern "C" void kernel_launch(void* const* d_in, const int* in_sizes, int n_in,
                              void* d_out, int out_size)
{
    const float* E  = (const float*)d_in[0];  // [N,200,64]
    const float* W  = (const float*)d_in[1];  // [64,64]
    const float* Lg = (const float*)d_in[2];  // [N,3,200]
    const int*   SL = (const int*)d_in[3];    // [N,1]
    float* out = (float*)d_out;               // [N,3,64]

    const int N = in_sizes[3];
    const int smem_bytes = SMEM_FLOATS * (int)sizeof(float);

    cudaFuncSetAttribute(caps_kernel,
                         cudaFuncAttributeMaxDynamicSharedMemorySize, smem_bytes);

    caps_kernel<<<N, 256, smem_bytes>>>(E, W, Lg, SL, out);
}